// round 3
// baseline (speedup 1.0000x reference)
#include <cuda_runtime.h>
#include <math.h>

#define N_PATHS 2048
#define N_STEPS 512
#define N_FWD   40
#define DT_F    (1.0f/512.0f)
#define SHIFT_F 0.02f
// DT^-0.4 / Gamma(0.6) = 2^3.6 / 1.4891922488128176 (pure math constant; avoids
// the fp64 tgamma software routine that cost ~8us on one thread)
#define SC_CONST 8.142489698f

// ---------------- device scratch (no allocations allowed) ----------------
__device__ float  d_g[N_STEPS];            // Toeplitz kernel taps g[k]
__device__ float  d_s2[N_STEPS];           // prefix sum of g^2
__device__ float  d_vs[N_FWD];             // vol_scale
__device__ float  d_mu0[N_FWD];            // mu_0
__device__ float4 d_fbm4[N_PATHS * N_STEPS];

// ---------------- f32x2 packed helpers (Blackwell FFMA2) ----------------
__device__ __forceinline__ unsigned long long pack2(float a, float b) {
    unsigned long long r;
    asm("mov.b64 %0, {%1, %2};" : "=l"(r) : "f"(a), "f"(b));
    return r;
}
__device__ __forceinline__ void unpack2(unsigned long long v, float& a, float& b) {
    asm("mov.b64 {%0, %1}, %2;" : "=f"(a), "=f"(b) : "l"(v));
}
__device__ __forceinline__ unsigned long long fma2(unsigned long long a,
                                                   unsigned long long b,
                                                   unsigned long long c) {
    unsigned long long d;
    asm("fma.rn.f32x2 %0, %1, %2, %3;" : "=l"(d) : "l"(a), "l"(b), "l"(c));
    return d;
}

// ---------------- K1: precompute g, s2, per-n constants (all fp32) ----------
// g[k] = ((k+1)^0.6 - k^0.6)/0.6 * SC. Cancellation-free:
// (k+1)^0.6 - k^0.6 = k^0.6 * expm1(0.6*log1p(1/k)).
__global__ void precompute_kernel(const float* __restrict__ F0,
                                  const float* __restrict__ alphas,
                                  const float* __restrict__ tau,
                                  const float* __restrict__ Lam) {
    const int t = threadIdx.x;

    float w;
    if (t == 0) {
        w = 1.0f / 0.6f;
    } else {
        float tf = (float)t;
        w = powf(tf, 0.6f) * expm1f(0.6f * log1pf(1.0f / tf)) * (1.0f / 0.6f);
    }
    const float gv = w * SC_CONST;
    d_g[t] = gv;

    __shared__ float ssum[N_STEPS];
    ssum[t] = gv * gv;
    __syncthreads();
    for (int off = 1; off < N_STEPS; off <<= 1) {
        float v = (t >= off) ? ssum[t - off] : 0.0f;
        __syncthreads();
        ssum[t] += v;
        __syncthreads();
    }
    d_s2[t] = ssum[t];

    __shared__ float som[N_FWD];
    if (t < N_FWD) {
        float vs = alphas[t] * sqrtf(fabsf(F0[t] + SHIFT_F));
        d_vs[t]  = vs;
        som[t]   = tau[t] * vs / (1.0f + tau[t] * F0[t]);
    }
    __syncthreads();
    if (t < N_FWD) {
        float acc = 0.0f;
        #pragma unroll 8
        for (int mcol = 0; mcol < N_FWD; mcol++)
            acc += Lam[t * N_FWD + mcol] * som[mcol];
        d_mu0[t] = -d_vs[t] * acc;
    }
}

// ---------------- K2: causal convolution fbm4[p,t,:] = sum_{s<=t} g[t-s] dz[p,s,:] --------
#define CONV_TPB 128
#define PPB 4
__global__ void __launch_bounds__(CONV_TPB, 4)
conv_kernel(const float4* __restrict__ dz) {
    __shared__ __align__(16) float  sgp[N_STEPS + 8];  // sgp[4+k] = g[k]; [0..3] = 0 pad
    __shared__ float4 sdz[PPB][N_STEPS];

    const int tid   = threadIdx.x;
    const int pbase = blockIdx.x * PPB;

    for (int i = tid; i < N_STEPS + 8; i += CONV_TPB)
        sgp[i] = (i >= 4 && i < N_STEPS + 4) ? d_g[i - 4] : 0.0f;
    #pragma unroll
    for (int q = 0; q < PPB; q++)
        for (int s = tid; s < N_STEPS; s += CONV_TPB)
            sdz[q][s] = dz[(pbase + q) * N_STEPS + s];
    __syncthreads();

    const int t0 = tid * 4;               // this thread owns t0..t0+3

    unsigned long long accA[PPB][4], accB[PPB][4];
    #pragma unroll
    for (int q = 0; q < PPB; q++)
        #pragma unroll
        for (int j = 0; j < 4; j++) { accA[q][j] = 0ull; accB[q][j] = 0ull; }

    // rolling window kept pre-packed: wjp = {g[t0+j-s], g[t0+j-s]}
    float4 wv = *(const float4*)&sgp[t0 + 4];
    unsigned long long w0p = pack2(wv.x, wv.x);
    unsigned long long w1p = pack2(wv.y, wv.y);
    unsigned long long w2p = pack2(wv.z, wv.z);
    unsigned long long w3p = pack2(wv.w, wv.w);

    for (int sb = 0; sb <= t0; sb += 4) {
        // next 4 entrants: g[t0-sb-4 .. t0-sb-1] (zero-padded below index 0)
        float4 gn = *(const float4*)&sgp[t0 - sb];
        #pragma unroll
        for (int i = 0; i < 4; i++) {
            const int s = sb + i;
            #pragma unroll
            for (int q = 0; q < PPB; q++) {
                float4 zv = sdz[q][s];
                unsigned long long zA = pack2(zv.x, zv.y);
                unsigned long long zB = pack2(zv.z, zv.w);
                accA[q][0] = fma2(w0p, zA, accA[q][0]);
                accB[q][0] = fma2(w0p, zB, accB[q][0]);
                accA[q][1] = fma2(w1p, zA, accA[q][1]);
                accB[q][1] = fma2(w1p, zB, accB[q][1]);
                accA[q][2] = fma2(w2p, zA, accA[q][2]);
                accB[q][2] = fma2(w2p, zB, accB[q][2]);
                accA[q][3] = fma2(w3p, zA, accA[q][3]);
                accB[q][3] = fma2(w3p, zB, accB[q][3]);
            }
            float gnew = (i == 0) ? gn.w : (i == 1) ? gn.z : (i == 2) ? gn.y : gn.x;
            w3p = w2p; w2p = w1p; w1p = w0p; w0p = pack2(gnew, gnew);
        }
    }

    #pragma unroll
    for (int q = 0; q < PPB; q++)
        #pragma unroll
        for (int j = 0; j < 4; j++) {
            float a, b, c, d;
            unpack2(accA[q][j], a, b);
            unpack2(accB[q][j], c, d);
            d_fbm4[(pbase + q) * N_STEPS + t0 + j] = make_float4(a, b, c, d);
        }
}

// ---------------- K3: fused mix / exp / dF / cumsum / store, 2 forwards/thread ----
#define PATH_TPB 256
#define NPT 2                              // forwards per thread
#define K3_THREADS (N_PATHS * (N_FWD / NPT))
__global__ void __launch_bounds__(PATH_TPB)
path_kernel(const float4* __restrict__ dz,
            const float*  __restrict__ F0,
            const float*  __restrict__ rhos,
            const float*  __restrict__ nus,
            const float*  __restrict__ loadings,
            float* __restrict__ out) {
    __shared__ float ss2[N_STEPS];
    for (int i = threadIdx.x; i < N_STEPS; i += PATH_TPB)
        ss2[i] = d_s2[i];
    __syncthreads();

    const int gid = blockIdx.x * PATH_TPB + threadIdx.x;
    if (gid >= K3_THREADS) return;
    const int p  = gid / (N_FWD / NPT);
    const int j  = gid - p * (N_FWD / NPT);
    const int n0 = j * NPT;
    const int n1 = n0 + 1;

    const float rho0 = rhos[n0],           rho1 = rhos[n1];
    const float nu0  = nus[n0],            nu1  = nus[n1];
    const float sq0  = sqrtf(fmaxf(1.0f - rho0 * rho0, 0.0f));
    const float sq1  = sqrtf(fmaxf(1.0f - rho1 * rho1, 0.0f));
    const float a0   = loadings[n0 * 3 + 0], a1 = loadings[n0 * 3 + 1], a2 = loadings[n0 * 3 + 2];
    const float b0   = loadings[n1 * 3 + 0], b1 = loadings[n1 * 3 + 1], b2 = loadings[n1 * 3 + 2];
    const float vs0  = d_vs[n0],           vs1  = d_vs[n1];
    const float mu0  = d_mu0[n0] * DT_F,   mu1  = d_mu0[n1] * DT_F;
    const float cv0  = 0.5f * nu0 * nu0 * DT_F;
    const float cv1  = 0.5f * nu1 * nu1 * DT_F;
    const float f00  = F0[n0],             f01  = F0[n1];

    const float4* fb  = d_fbm4 + (size_t)p * N_STEPS;
    const float4* dzp = dz     + (size_t)p * N_STEPS;
    float* op = out + (size_t)p * (N_STEPS + 1) * N_FWD + n0;

    float acc0 = f00, acc1 = f01;
    __stcs((float2*)op, make_float2(f00, f01));
    op += N_FWD;

    for (int t = 0; t < N_STEPS; t++) {
        float4 f = fb[t];
        float4 z = dzp[t];
        float s2v = ss2[t];
        float crv = f.x * a0 + f.y * a1 + f.z * a2;
        float crw = f.x * b0 + f.y * b1 + f.z * b2;
        float wr0 = z.x * a0 + z.y * a1 + z.z * a2;
        float wr1 = z.x * b0 + z.y * b1 + z.z * b2;
        float u0  = __expf(nu0 * (rho0 * crv + sq0 * f.w) - cv0 * s2v);
        float u1  = __expf(nu1 * (rho1 * crw + sq1 * f.w) - cv1 * s2v);
        acc0 += mu0 * (u0 * u0) + wr0 * (u0 * vs0);
        acc1 += mu1 * (u1 * u1) + wr1 * (u1 * vs1);
        __stcs((float2*)op, make_float2(acc0, acc1));
        op += N_FWD;
    }
}

// ---------------- launcher ----------------
extern "C" void kernel_launch(void* const* d_in, const int* in_sizes, int n_in,
                              void* d_out, int out_size) {
    const float* dz       = (const float*)d_in[0];   // (2048, 512, 4)
    const float* F0       = (const float*)d_in[1];   // (40,)
    const float* alphas   = (const float*)d_in[2];   // (40,)
    const float* rhos     = (const float*)d_in[3];   // (40,)
    const float* nus      = (const float*)d_in[4];   // (40,)
    const float* tau      = (const float*)d_in[5];   // (40,)
    const float* loadings = (const float*)d_in[6];   // (40, 3)
    const float* Lam      = (const float*)d_in[7];   // (40, 40)
    float* out = (float*)d_out;                      // (2048, 513, 40)

    precompute_kernel<<<1, N_STEPS>>>(F0, alphas, tau, Lam);
    conv_kernel<<<N_PATHS / PPB, CONV_TPB>>>((const float4*)dz);
    path_kernel<<<(K3_THREADS + PATH_TPB - 1) / PATH_TPB, PATH_TPB>>>(
        (const float4*)dz, F0, rhos, nus, loadings, out);
}

// round 4
// speedup vs baseline: 1.6925x; 1.6925x over previous
#include <cuda_runtime.h>
#include <math.h>

#define N_PATHS 2048
#define N_STEPS 512
#define N_FWD   40
#define DT_F    (1.0f/512.0f)
#define SHIFT_F 0.02f
// DT^-0.4 / Gamma(0.6) = 2^3.6 / 1.4891922488128176  (pure math constant)
#define SC_CONST 8.142489698f

// ---------------- device scratch ----------------
__device__ float d_g[N_STEPS];             // Toeplitz kernel taps g[k]
__device__ float d_s2[N_STEPS];            // prefix sum of g^2
__device__ float d_vs[N_FWD];              // vol_scale
__device__ float d_mu0[N_FWD];             // mu_0

// ---------------- f32x2 packed helpers (Blackwell FFMA2) ----------------
__device__ __forceinline__ unsigned long long pack2(float a, float b) {
    unsigned long long r;
    asm("mov.b64 %0, {%1, %2};" : "=l"(r) : "f"(a), "f"(b));
    return r;
}
__device__ __forceinline__ void unpack2(unsigned long long v, float& a, float& b) {
    asm("mov.b64 {%0, %1}, %2;" : "=f"(a), "=f"(b) : "l"(v));
}
__device__ __forceinline__ unsigned long long fma2(unsigned long long a,
                                                   unsigned long long b,
                                                   unsigned long long c) {
    unsigned long long d;
    asm("fma.rn.f32x2 %0, %1, %2, %3;" : "=l"(d) : "l"(a), "l"(b), "l"(c));
    return d;
}

// ---------------- K1: precompute g, s2, per-n constants (all fp32) ----------
// g[k] = ((k+1)^0.6 - k^0.6)/0.6 * SC, cancellation-free:
// (k+1)^0.6 - k^0.6 = k^0.6 * expm1(0.6*log1p(1/k)).
__global__ void precompute_kernel(const float* __restrict__ F0,
                                  const float* __restrict__ alphas,
                                  const float* __restrict__ tau,
                                  const float* __restrict__ Lam) {
    const int t    = threadIdx.x;
    const int lane = t & 31;
    const int w    = t >> 5;

    float wgt;
    if (t == 0) {
        wgt = 1.0f / 0.6f;
    } else {
        float tf = (float)t;
        wgt = powf(tf, 0.6f) * expm1f(0.6f * log1pf(1.0f / tf)) * (1.0f / 0.6f);
    }
    const float gv = wgt * SC_CONST;
    d_g[t] = gv;

    // warp-shuffle inclusive scan of gv^2 (3 barriers total)
    float v = gv * gv;
    #pragma unroll
    for (int o = 1; o < 32; o <<= 1) {
        float nv = __shfl_up_sync(0xffffffffu, v, o);
        if (lane >= o) v += nv;
    }
    __shared__ float wsum[16];
    if (lane == 31) wsum[w] = v;
    __syncthreads();
    if (w == 0 && lane < 16) {
        float s = wsum[lane];
        #pragma unroll
        for (int o = 1; o < 16; o <<= 1) {
            float nv = __shfl_up_sync(0xffffu, s, o);
            if (lane >= o) s += nv;
        }
        wsum[lane] = s;
    }
    __syncthreads();
    d_s2[t] = v + ((w > 0) ? wsum[w - 1] : 0.0f);

    __shared__ float som[N_FWD];
    if (t < N_FWD) {
        float vs = alphas[t] * sqrtf(fabsf(F0[t] + SHIFT_F));
        d_vs[t]  = vs;
        som[t]   = tau[t] * vs / (1.0f + tau[t] * F0[t]);
    }
    __syncthreads();
    if (t < N_FWD) {
        float acc = 0.0f;
        #pragma unroll 8
        for (int mcol = 0; mcol < N_FWD; mcol++)
            acc += Lam[t * N_FWD + mcol] * som[mcol];
        d_mu0[t] = -d_vs[t] * acc;
    }
}

// ---------------- fused K2+K3 -------------------------------------------------
// Phase 1 (tid<128): causal convolution into SMEM (R2 inner loop, PPB=2 paths).
// Phase 2 (tid<80) : per-(path,n) mix/exp/dF/cumsum, all operands from SMEM.
#define PPB 2
#define FUSED_TPB 128
#define PH2_THREADS (PPB * N_FWD)          // 80

__global__ void __launch_bounds__(FUSED_TPB)
fused_kernel(const float4* __restrict__ dz,
             const float*  __restrict__ F0,
             const float*  __restrict__ rhos,
             const float*  __restrict__ nus,
             const float*  __restrict__ loadings,
             float* __restrict__ out) {
    __shared__ __align__(16) float4 sdz [PPB * N_STEPS];   // 16 KB
    __shared__ __align__(16) float4 sfbm[PPB * N_STEPS];   // 16 KB
    __shared__ __align__(16) float  sgp [N_STEPS + 8];     // sgp[4+k]=g[k], [0..3]=0
    __shared__ float  ss2[N_STEPS];

    const int tid   = threadIdx.x;
    const int pbase = blockIdx.x * PPB;

    for (int i = tid; i < N_STEPS + 8; i += FUSED_TPB)
        sgp[i] = (i >= 4 && i < N_STEPS + 4) ? d_g[i - 4] : 0.0f;
    for (int i = tid; i < N_STEPS; i += FUSED_TPB)
        ss2[i] = d_s2[i];
    for (int i = tid; i < PPB * N_STEPS; i += FUSED_TPB)
        sdz[i] = dz[(size_t)pbase * N_STEPS + i];
    __syncthreads();

    // ---------------- phase 1: convolution ----------------
    {
        const int t0 = tid * 4;            // this thread owns t0..t0+3

        unsigned long long accA[PPB][4], accB[PPB][4];
        #pragma unroll
        for (int q = 0; q < PPB; q++)
            #pragma unroll
            for (int j = 0; j < 4; j++) { accA[q][j] = 0ull; accB[q][j] = 0ull; }

        // rolling window w[j] = g[t0 + j - s]
        float4 wv = *(const float4*)&sgp[t0 + 4];
        float w0 = wv.x, w1 = wv.y, w2 = wv.z, w3 = wv.w;

        for (int sb = 0; sb <= t0; sb += 4) {
            float4 gn = *(const float4*)&sgp[t0 - sb];
            #pragma unroll
            for (int i = 0; i < 4; i++) {
                const int s = sb + i;
                unsigned long long gw0 = pack2(w0, w0);
                unsigned long long gw1 = pack2(w1, w1);
                unsigned long long gw2 = pack2(w2, w2);
                unsigned long long gw3 = pack2(w3, w3);
                #pragma unroll
                for (int q = 0; q < PPB; q++) {
                    float4 zv = sdz[q * N_STEPS + s];
                    unsigned long long zA = pack2(zv.x, zv.y);
                    unsigned long long zB = pack2(zv.z, zv.w);
                    accA[q][0] = fma2(gw0, zA, accA[q][0]);
                    accB[q][0] = fma2(gw0, zB, accB[q][0]);
                    accA[q][1] = fma2(gw1, zA, accA[q][1]);
                    accB[q][1] = fma2(gw1, zB, accB[q][1]);
                    accA[q][2] = fma2(gw2, zA, accA[q][2]);
                    accB[q][2] = fma2(gw2, zB, accB[q][2]);
                    accA[q][3] = fma2(gw3, zA, accA[q][3]);
                    accB[q][3] = fma2(gw3, zB, accB[q][3]);
                }
                float gnew = (i == 0) ? gn.w : (i == 1) ? gn.z : (i == 2) ? gn.y : gn.x;
                w3 = w2; w2 = w1; w1 = w0; w0 = gnew;
            }
        }

        #pragma unroll
        for (int q = 0; q < PPB; q++)
            #pragma unroll
            for (int j = 0; j < 4; j++) {
                float a, b, c, d;
                unpack2(accA[q][j], a, b);
                unpack2(accB[q][j], c, d);
                sfbm[q * N_STEPS + t0 + j] = make_float4(a, b, c, d);
            }
    }
    __syncthreads();

    // ---------------- phase 2: mix / exp / dF / cumsum / store ----------------
    if (tid < PH2_THREADS) {
        const int q = tid / N_FWD;
        const int n = tid - q * N_FWD;
        const int p = pbase + q;

        const float rho = rhos[n];
        const float nu  = nus[n];
        const float sq  = sqrtf(fmaxf(1.0f - rho * rho, 0.0f));
        const float l0  = loadings[n * 3 + 0];
        const float l1  = loadings[n * 3 + 1];
        const float l2  = loadings[n * 3 + 2];
        const float vs   = d_vs[n];
        const float muDT = d_mu0[n] * DT_F;
        const float cvar = 0.5f * nu * nu * DT_F;
        const float f0   = F0[n];

        const float4* fb  = sfbm + q * N_STEPS;
        const float4* zp  = sdz  + q * N_STEPS;
        float* op = out + (size_t)p * (N_STEPS + 1) * N_FWD + n;

        float acc = f0;
        __stcs(op, f0);
        op += N_FWD;

        for (int t = 0; t < N_STEPS; t++) {
            float4 f = fb[t];
            float4 z = zp[t];
            float fbm_curve = f.x * l0 + f.y * l1 + f.z * l2;
            float fbm = rho * fbm_curve + sq * f.w;
            float wr  = z.x * l0 + z.y * l1 + z.z * l2;
            float u   = __expf(nu * fbm - cvar * ss2[t]);
            acc += muDT * (u * u) + wr * (u * vs);
            __stcs(op, acc);
            op += N_FWD;
        }
    }
}

// ---------------- launcher ----------------
extern "C" void kernel_launch(void* const* d_in, const int* in_sizes, int n_in,
                              void* d_out, int out_size) {
    const float* dz       = (const float*)d_in[0];   // (2048, 512, 4)
    const float* F0       = (const float*)d_in[1];   // (40,)
    const float* alphas   = (const float*)d_in[2];   // (40,)
    const float* rhos     = (const float*)d_in[3];   // (40,)
    const float* nus      = (const float*)d_in[4];   // (40,)
    const float* tau      = (const float*)d_in[5];   // (40,)
    const float* loadings = (const float*)d_in[6];   // (40, 3)
    const float* Lam      = (const float*)d_in[7];   // (40, 40)
    float* out = (float*)d_out;                      // (2048, 513, 40)

    precompute_kernel<<<1, N_STEPS>>>(F0, alphas, tau, Lam);
    fused_kernel<<<N_PATHS / PPB, FUSED_TPB>>>(
        (const float4*)dz, F0, rhos, nus, loadings, out);
}